// round 2
// baseline (speedup 1.0000x reference)
#include <cuda_runtime.h>

#define Bx 4
#define Lx 512
#define Dx 128
#define TI 8
#define TJ 32
#define LOG2E 1.4426950408889634f

// Scratch (static device arrays: allowed; no allocations anywhere)
__device__ float g_Q[Bx * Lx * Dx];
__device__ float g_K[Bx * Lx * Dx];

__device__ __forceinline__ float tanh_fast(float v) {
    float y;
    asm("tanh.approx.f32 %0, %1;" : "=f"(y) : "f"(v));
    return y;
}
__device__ __forceinline__ float ex2_fast(float v) {
    float y;
    asm("ex2.approx.f32 %0, %1;" : "=f"(y) : "f"(v));
    return y;
}

// ---------------------------------------------------------------------------
// Kernel 1: Q = x @ Wq^T + bq ; K = x @ Wk^T + bk
// 8 rows per block (grid 256 > 148 SMs), 256 threads: 0..127 -> Q col e,
// 128..255 -> K col e. W rows streamed unroll-8 (MLP), L1-resident after warm.
// ---------------------------------------------------------------------------
__global__ __launch_bounds__(256) void qk_kernel(
        const float* __restrict__ x,
        const float* __restrict__ Wq, const float* __restrict__ bq,
        const float* __restrict__ Wk, const float* __restrict__ bk) {
    __shared__ float4 xs[TI][32];
    int row0 = blockIdx.x * TI;
    int e = threadIdx.x & 127;
    int which = threadIdx.x >> 7;

    const float4* x4 = (const float4*)(x + (size_t)row0 * Dx);
    ((float4*)xs)[threadIdx.x] = x4[threadIdx.x];   // 8*32 = 256 float4
    __syncthreads();

    const float* W = which ? Wk : Wq;
    float bias = which ? bk[e] : bq[e];
    const float4* W4 = (const float4*)(W + (size_t)e * Dx);

    float acc[TI];
#pragma unroll
    for (int r = 0; r < TI; r++) acc[r] = 0.f;

#pragma unroll 8
    for (int d4 = 0; d4 < 32; d4++) {
        float4 wv = __ldg(&W4[d4]);
#pragma unroll
        for (int r = 0; r < TI; r++) {
            float4 xv = xs[r][d4];
            acc[r] += wv.x * xv.x + wv.y * xv.y + wv.z * xv.z + wv.w * xv.w;
        }
    }

    float* o = which ? g_K : g_Q;
#pragma unroll
    for (int r = 0; r < TI; r++)
        o[(size_t)(row0 + r) * Dx + e] = acc[r] + bias;
}

// ---------------------------------------------------------------------------
// Kernel 2 (fused): for TI=8 query rows:
//   s[i][j] = sum_d (w[d]*log2e) * tanh(Q[i,d] + K[j,d])        (bw dropped:
//             constant shift cancels in softmax)
//   p = exp2(s)      (no max subtraction: |s| <= sum|w| ~ 9, fp32-safe)
//   O[i] = (sum_j p[i][j] * x[j]) / sum_j p[i][j]
// 128 threads. Score phase: thread (ty=tid>>4, tx=tid&15) computes cols
// (2tx, 2tx+1) of row ty -> K read as one LDS.64 from transposed Kst.
// AV phase: thread owns column d=tid for all 8 rows (acc[8]).
// ---------------------------------------------------------------------------
__global__ __launch_bounds__(128) void attn_kernel(
        const float* __restrict__ x,
        const float* __restrict__ w,
        float* __restrict__ out) {
    __shared__ __align__(16) float Kst[Dx][TJ + 2];   // [128][34] transposed, pad even for float2
    __shared__ __align__(16) float xs[TJ][Dx];        // [32][128] natural
    __shared__ float Qst[Dx][9];                      // transposed Q tile, odd pad
    __shared__ __align__(16) float Ps[TI][36];        // pad mult-of-4 for float4 reads
    __shared__ float ws[Dx];
    __shared__ float sinv[TI];

    int tid = threadIdx.x;
    int b = blockIdx.y;
    int i0 = blockIdx.x * TI;

    const float* Qb = g_Q + ((size_t)b * Lx + i0) * Dx;
    const float* Kb = g_K + (size_t)b * Lx * Dx;
    const float* xb = x + (size_t)b * Lx * Dx;

    ws[tid] = w[tid] * LOG2E;                         // tid in [0,128)
    for (int t = tid; t < TI * Dx; t += 128) {        // Q tile -> transposed
        int r = t >> 7, d = t & 127;
        Qst[d][r] = Qb[t];
    }

    int ty = tid >> 4;          // query row 0..7
    int tx = tid & 15;          // col pair (2tx, 2tx+1)

    float acc[TI];
#pragma unroll
    for (int r = 0; r < TI; r++) acc[r] = 0.f;
    float psum = 0.f;

    for (int j0 = 0; j0 < Lx; j0 += TJ) {
        __syncthreads();        // prior AV done (and initial Qst/ws fill)
        // Stage K chunk transposed + x chunk natural (both coalesced float4 in)
        const float4* Kb4 = (const float4*)(Kb + (size_t)j0 * Dx);
        const float4* xb4 = (const float4*)(xb + (size_t)j0 * Dx);
#pragma unroll
        for (int t = tid; t < TJ * Dx / 4; t += 128) {
            float4 v = Kb4[t];
            int r = t >> 5, d = (t & 31) * 4;
            Kst[d][r] = v.x; Kst[d + 1][r] = v.y;
            Kst[d + 2][r] = v.z; Kst[d + 3][r] = v.w;
            ((float4*)xs)[t] = xb4[t];
        }
        __syncthreads();

        // Score: 2 tanh per d-step, MUFU-bound
        float a0 = 0.f, a1 = 0.f;
#pragma unroll 32
        for (int d = 0; d < Dx; d++) {
            float q = Qst[d][ty];
            float2 k = *(const float2*)&Kst[d][2 * tx];
            float wl = ws[d];
            a0 += wl * tanh_fast(q + k.x);
            a1 += wl * tanh_fast(q + k.y);
        }
        float p0 = ex2_fast(a0);
        float p1 = ex2_fast(a1);
        psum += p0 + p1;
        *(float2*)&Ps[ty][2 * tx] = make_float2(p0, p1);
        __syncthreads();

        // AV: O[r][d] += sum_j P[r][j] * x[j][d]
        int d = tid;
#pragma unroll
        for (int j4 = 0; j4 < TJ / 4; j4++) {
            float x0 = xs[4 * j4 + 0][d];
            float x1 = xs[4 * j4 + 1][d];
            float x2 = xs[4 * j4 + 2][d];
            float x3 = xs[4 * j4 + 3][d];
#pragma unroll
            for (int r = 0; r < TI; r++) {
                float4 p = *(const float4*)&Ps[r][4 * j4];
                acc[r] += p.x * x0 + p.y * x1 + p.z * x2 + p.w * x3;
            }
        }
    }

    // Row sums: reduce psum over the 16 lanes sharing ty (xor over low 4 bits)
#pragma unroll
    for (int o = 8; o; o >>= 1)
        psum += __shfl_xor_sync(0xffffffffu, psum, o);
    if (tx == 0) sinv[ty] = 1.0f / psum;
    __syncthreads();

    float* ob = out + ((size_t)b * Lx + i0) * Dx;
    int d = tid;
#pragma unroll
    for (int r = 0; r < TI; r++)
        ob[(size_t)r * Dx + d] = acc[r] * sinv[r];
}

// ---------------------------------------------------------------------------
extern "C" void kernel_launch(void* const* d_in, const int* in_sizes, int n_in,
                              void* d_out, int out_size) {
    const float* x  = (const float*)d_in[0];
    // d_in[1] = mask (bool) — intentionally unused: reference's masked_fill is
    // out-of-place and discarded, so mask has no effect on the output.
    const float* Wq = (const float*)d_in[2];
    const float* bq = (const float*)d_in[3];
    const float* Wk = (const float*)d_in[4];
    const float* bk = (const float*)d_in[5];
    const float* w  = (const float*)d_in[6];
    // d_in[7] = bw — unused: constant score shift cancels in softmax.
    float* out = (float*)d_out;

    qk_kernel<<<Bx * Lx / TI, 256>>>(x, Wq, bq, Wk, bk);

    dim3 g2(Lx / TI, Bx);
    attn_kernel<<<g2, 128>>>(x, w, out);
}

// round 3
// speedup vs baseline: 1.0420x; 1.0420x over previous
#include <cuda_runtime.h>
#include <cuda_fp16.h>

#define Bx 4
#define Lx 512
#define Dx 128
#define LOG2E 1.4426950408889634f

// Scratch (static device arrays: allowed; no allocations anywhere)
__device__ float g_Q[Bx * Lx * Dx];
__device__ float g_K[Bx * Lx * Dx];
__device__ float g_S[(size_t)Bx * Lx * Lx];

__device__ __forceinline__ unsigned tanh2(unsigned v) {
    unsigned y;
    asm("tanh.approx.f16x2 %0, %1;" : "=r"(y) : "r"(v));
    return y;
}
__device__ __forceinline__ unsigned hadd2u(unsigned a, unsigned b) {
    unsigned y;
    asm("add.rn.f16x2 %0, %1, %2;" : "=r"(y) : "r"(a), "r"(b));
    return y;
}
__device__ __forceinline__ float2 h2_to_f2(unsigned h) {
    __half2 hh = *reinterpret_cast<__half2*>(&h);
    return __half22float2(hh);
}
__device__ __forceinline__ unsigned pack_h2(float x, float y) {
    __half2 h = __float22half2_rn(make_float2(x, y));
    return *reinterpret_cast<unsigned*>(&h);
}

// ---------------------------------------------------------------------------
// Kernel 1: Q = x @ Wq^T + bq ; K = x @ Wk^T + bk
// 4 rows per block (grid 512), 256 threads: 0..127 -> Q col e, 128..255 -> K.
// ---------------------------------------------------------------------------
__global__ __launch_bounds__(256) void qk_kernel(
        const float* __restrict__ x,
        const float* __restrict__ Wq, const float* __restrict__ bq,
        const float* __restrict__ Wk, const float* __restrict__ bk) {
    __shared__ float4 xs[4][32];
    int row0 = blockIdx.x * 4;
    int e = threadIdx.x & 127;
    int which = threadIdx.x >> 7;

    const float4* x4 = (const float4*)(x + (size_t)row0 * Dx);
    if (threadIdx.x < 128) ((float4*)xs)[threadIdx.x] = x4[threadIdx.x];
    __syncthreads();

    const float* W = which ? Wk : Wq;
    float bias = which ? bk[e] : bq[e];
    const float4* W4 = (const float4*)(W + (size_t)e * Dx);

    float acc[4] = {0.f, 0.f, 0.f, 0.f};

#pragma unroll 8
    for (int d4 = 0; d4 < 32; d4++) {
        float4 wv = __ldg(&W4[d4]);
#pragma unroll
        for (int r = 0; r < 4; r++) {
            float4 xv = xs[r][d4];
            acc[r] += wv.x * xv.x + wv.y * xv.y + wv.z * xv.z + wv.w * xv.w;
        }
    }

    float* o = which ? g_K : g_Q;
#pragma unroll
    for (int r = 0; r < 4; r++)
        o[(size_t)(row0 + r) * Dx + e] = acc[r] + bias;
}

// ---------------------------------------------------------------------------
// Kernel 2: S[b,i,j] = sum_d (w[d]*log2e) * tanh(Q[b,i,d]+K[b,j,d])
// (bw dropped: constant shift cancels in softmax; log2e folded into w.)
// Block tile: 16 i-rows x 64 j-cols, 256 threads; thread (ty=i, tx) handles
// j = tx + 16c, c=0..3. Q/K staged as half2 paired over d -> one
// tanh.approx.f16x2 covers 2 d-terms. f32 accumulation (F2F + FFMA).
// ---------------------------------------------------------------------------
__global__ __launch_bounds__(256) void score_kernel(const float* __restrict__ w) {
    __shared__ unsigned Qsh[16][65];   // [i][d-pair] half2
    __shared__ unsigned Ksh[64][65];   // [j][d-pair] half2
    __shared__ float wsf[Dx];

    int tid = threadIdx.x;
    int b = blockIdx.z;
    int i0 = blockIdx.y * 16;
    int j0 = blockIdx.x * 64;

    const float* Qb = g_Q + ((size_t)b * Lx + i0) * Dx;
    const float* Kb = g_K + ((size_t)b * Lx + j0) * Dx;

    if (tid < Dx) wsf[tid] = w[tid] * LOG2E;

    // Stage Q (16x128 f32 = 512 float4) -> half2 pairs over d
    const float4* Qb4 = (const float4*)Qb;
#pragma unroll
    for (int t = tid; t < 512; t += 256) {
        float4 v = Qb4[t];
        int r = t >> 5, c4 = t & 31;
        Qsh[r][2 * c4]     = pack_h2(v.x, v.y);
        Qsh[r][2 * c4 + 1] = pack_h2(v.z, v.w);
    }
    // Stage K (64x128 f32 = 2048 float4)
    const float4* Kb4 = (const float4*)Kb;
#pragma unroll
    for (int t = tid; t < 2048; t += 256) {
        float4 v = Kb4[t];
        int r = t >> 5, c4 = t & 31;
        Ksh[r][2 * c4]     = pack_h2(v.x, v.y);
        Ksh[r][2 * c4 + 1] = pack_h2(v.z, v.w);
    }
    __syncthreads();

    int ty = tid >> 4;   // i row 0..15
    int tx = tid & 15;   // j base; cols tx, tx+16, tx+32, tx+48

    float a0 = 0.f, a1 = 0.f, a2 = 0.f, a3 = 0.f;

#pragma unroll 8
    for (int dp = 0; dp < Dx / 2; dp++) {
        unsigned qq = Qsh[ty][dp];
        float2 wv = *(const float2*)&wsf[2 * dp];

        unsigned t0 = tanh2(hadd2u(qq, Ksh[tx][dp]));
        unsigned t1 = tanh2(hadd2u(qq, Ksh[tx + 16][dp]));
        unsigned t2 = tanh2(hadd2u(qq, Ksh[tx + 32][dp]));
        unsigned t3 = tanh2(hadd2u(qq, Ksh[tx + 48][dp]));

        float2 f0 = h2_to_f2(t0);
        float2 f1 = h2_to_f2(t1);
        float2 f2 = h2_to_f2(t2);
        float2 f3 = h2_to_f2(t3);

        a0 += wv.x * f0.x + wv.y * f0.y;
        a1 += wv.x * f1.x + wv.y * f1.y;
        a2 += wv.x * f2.x + wv.y * f2.y;
        a3 += wv.x * f3.x + wv.y * f3.y;
    }

    float* Sb = g_S + (((size_t)b * Lx + i0 + ty) * Lx + j0);
    Sb[tx]      = a0;
    Sb[tx + 16] = a1;
    Sb[tx + 32] = a2;
    Sb[tx + 48] = a3;
}

// ---------------------------------------------------------------------------
// Kernel 3: softmax over j (scores already log2e-scaled -> exp2 direct)
// + out = attn @ x. 16 query rows per block, 256 threads.
// ---------------------------------------------------------------------------
__global__ __launch_bounds__(256) void out_kernel(const float* __restrict__ x,
                                                  float* __restrict__ out) {
    __shared__ float Ps[16][Lx];   // 32 KB
    __shared__ float linv[16];

    int row0 = blockIdx.x * 16;        // global row in [0, B*L)
    int bb = row0 >> 9;                // / L

    const float4* S4 = (const float4*)(g_S + (size_t)row0 * Lx);
    for (int t = threadIdx.x; t < 16 * Lx / 4; t += 256)
        ((float4*)Ps)[t] = S4[t];
    __syncthreads();

    int warp = threadIdx.x >> 5;
    int lane = threadIdx.x & 31;

#pragma unroll
    for (int rr = 0; rr < 2; rr++) {
        int r = warp * 2 + rr;
        float v[16];
        float m = -1e30f;
#pragma unroll
        for (int c = 0; c < 16; c++) {
            v[c] = Ps[r][lane + c * 32];
            m = fmaxf(m, v[c]);
        }
#pragma unroll
        for (int o = 16; o; o >>= 1) m = fmaxf(m, __shfl_xor_sync(0xffffffffu, m, o));
        float s = 0.f;
#pragma unroll
        for (int c = 0; c < 16; c++) {
            float e = exp2f(v[c] - m);   // scores already include log2e
            s += e;
            Ps[r][lane + c * 32] = e;
        }
#pragma unroll
        for (int o = 16; o; o >>= 1) s += __shfl_xor_sync(0xffffffffu, s, o);
        if (lane == 0) linv[r] = 1.0f / s;
    }
    __syncthreads();

    int d = threadIdx.x & 127;
    int ig = threadIdx.x >> 7;   // 0 -> rows 0..7, 1 -> rows 8..15
    const float* xb = x + (size_t)bb * Lx * Dx;

    float acc[8];
#pragma unroll
    for (int r = 0; r < 8; r++) acc[r] = 0.f;

    for (int j = 0; j < Lx; j += 4) {
        float xv0 = xb[(size_t)(j + 0) * Dx + d];
        float xv1 = xb[(size_t)(j + 1) * Dx + d];
        float xv2 = xb[(size_t)(j + 2) * Dx + d];
        float xv3 = xb[(size_t)(j + 3) * Dx + d];
#pragma unroll
        for (int r = 0; r < 8; r++) {
            float4 p = *(const float4*)&Ps[ig * 8 + r][j];
            acc[r] += p.x * xv0 + p.y * xv1 + p.z * xv2 + p.w * xv3;
        }
    }

#pragma unroll
    for (int r = 0; r < 8; r++) {
        int row = row0 + ig * 8 + r;
        out[(size_t)row * Dx + d] = acc[r] * linv[ig * 8 + r];
    }
}

// ---------------------------------------------------------------------------
extern "C" void kernel_launch(void* const* d_in, const int* in_sizes, int n_in,
                              void* d_out, int out_size) {
    const float* x  = (const float*)d_in[0];
    // d_in[1] = mask (bool) — intentionally unused: reference's masked_fill is
    // out-of-place and discarded, so mask has no effect on the output.
    const float* Wq = (const float*)d_in[2];
    const float* bq = (const float*)d_in[3];
    const float* Wk = (const float*)d_in[4];
    const float* bk = (const float*)d_in[5];
    const float* w  = (const float*)d_in[6];
    // d_in[7] = bw — unused: constant score shift cancels in softmax.
    float* out = (float*)d_out;

    qk_kernel<<<Bx * Lx / 4, 256>>>(x, Wq, bq, Wk, bk);

    dim3 g2(Lx / 64, Lx / 16, Bx);
    score_kernel<<<g2, 256>>>(w);

    out_kernel<<<Bx * Lx / 16, 256>>>(x, out);
}

// round 4
// speedup vs baseline: 1.1170x; 1.0719x over previous
#include <cuda_runtime.h>
#include <cuda_fp16.h>

#define Bx 4
#define Lx 512
#define Dx 128
#define LOG2E 1.4426950408889634f

// Scratch (static device arrays: allowed; no allocations anywhere)
__device__ float g_Q[Bx * Lx * Dx];
__device__ float g_K[Bx * Lx * Dx];
__device__ float g_S[(size_t)Bx * Lx * Lx];

__device__ __forceinline__ unsigned tanh2(unsigned v) {
    unsigned y;
    asm("tanh.approx.f16x2 %0, %1;" : "=r"(y) : "r"(v));
    return y;
}
__device__ __forceinline__ unsigned hadd2u(unsigned a, unsigned b) {
    unsigned y;
    asm("add.rn.f16x2 %0, %1, %2;" : "=r"(y) : "r"(a), "r"(b));
    return y;
}
__device__ __forceinline__ float2 h2_to_f2(unsigned h) {
    __half2 hh = *reinterpret_cast<__half2*>(&h);
    return __half22float2(hh);
}
__device__ __forceinline__ unsigned pack_h2(float x, float y) {
    __half2 h = __float22half2_rn(make_float2(x, y));
    return *reinterpret_cast<unsigned*>(&h);
}

// ---------------------------------------------------------------------------
// Kernel 1: Q = x @ Wq^T + bq ; K = x @ Wk^T + bk   (R2-exact config: the
// empirically fastest grid/rows point — W re-read per block scales with grid,
// latency hiding needs >=2 blocks/SM; grid 256 is the sweet spot.)
// ---------------------------------------------------------------------------
__global__ __launch_bounds__(256) void qk_kernel(
        const float* __restrict__ x,
        const float* __restrict__ Wq, const float* __restrict__ bq,
        const float* __restrict__ Wk, const float* __restrict__ bk) {
    __shared__ float4 xs[8][32];
    int row0 = blockIdx.x * 8;
    int e = threadIdx.x & 127;
    int which = threadIdx.x >> 7;

    const float4* x4 = (const float4*)(x + (size_t)row0 * Dx);
    ((float4*)xs)[threadIdx.x] = x4[threadIdx.x];   // 8*32 = 256 float4
    __syncthreads();

    const float* W = which ? Wk : Wq;
    float bias = which ? bk[e] : bq[e];
    const float4* W4 = (const float4*)(W + (size_t)e * Dx);

    float acc[8];
#pragma unroll
    for (int r = 0; r < 8; r++) acc[r] = 0.f;

#pragma unroll 8
    for (int d4 = 0; d4 < 32; d4++) {
        float4 wv = __ldg(&W4[d4]);
#pragma unroll
        for (int r = 0; r < 8; r++) {
            float4 xv = xs[r][d4];
            acc[r] += wv.x * xv.x + wv.y * xv.y + wv.z * xv.z + wv.w * xv.w;
        }
    }

    float* o = which ? g_K : g_Q;
#pragma unroll
    for (int r = 0; r < 8; r++)
        o[(size_t)(row0 + r) * Dx + e] = acc[r] + bias;
}

// ---------------------------------------------------------------------------
// Kernel 2: S[b,i,j] = sum_d (w[d]*log2e) * tanh(Q[b,i,d]+K[b,j,d])
// (bw dropped: cancels in softmax; log2e folded into w.)
// Tile 16i x 128j, 256 threads; thread (ty=i, tx) handles j = tx + 16c,
// c=0..7 (8 K-LDS amortize 1 Q-LDS + 1 w-LDS). half2-paired over d; one
// tanh.approx.f16x2 covers 2 d-terms; f32 accumulation.
// ---------------------------------------------------------------------------
__global__ __launch_bounds__(256) void score_kernel(const float* __restrict__ w) {
    __shared__ unsigned Qsh[16][65];    // [i][d-pair] half2
    __shared__ unsigned Ksh[128][65];   // [j][d-pair] half2
    __shared__ float2 wsf[Dx / 2];

    int tid = threadIdx.x;
    int b = blockIdx.z;
    int i0 = blockIdx.y * 16;
    int j0 = blockIdx.x * 128;

    const float* Qb = g_Q + ((size_t)b * Lx + i0) * Dx;
    const float* Kb = g_K + ((size_t)b * Lx + j0) * Dx;

    if (tid < Dx / 2) {
        float2 wv = ((const float2*)w)[tid];
        wsf[tid] = make_float2(wv.x * LOG2E, wv.y * LOG2E);
    }

    // Stage Q (16x128 f32 = 512 float4) -> half2 pairs over d
    const float4* Qb4 = (const float4*)Qb;
#pragma unroll
    for (int t = tid; t < 512; t += 256) {
        float4 v = Qb4[t];
        int r = t >> 5, c4 = t & 31;
        Qsh[r][2 * c4]     = pack_h2(v.x, v.y);
        Qsh[r][2 * c4 + 1] = pack_h2(v.z, v.w);
    }
    // Stage K (128x128 f32 = 4096 float4)
    const float4* Kb4 = (const float4*)Kb;
#pragma unroll
    for (int t = tid; t < 4096; t += 256) {
        float4 v = Kb4[t];
        int r = t >> 5, c4 = t & 31;
        Ksh[r][2 * c4]     = pack_h2(v.x, v.y);
        Ksh[r][2 * c4 + 1] = pack_h2(v.z, v.w);
    }
    __syncthreads();

    int ty = tid >> 4;   // i row 0..15
    int tx = tid & 15;   // j base; cols tx + 16c, c = 0..7

    float a[8];
#pragma unroll
    for (int c = 0; c < 8; c++) a[c] = 0.f;

#pragma unroll 4
    for (int dp = 0; dp < Dx / 2; dp++) {
        unsigned qq = Qsh[ty][dp];
        float2 wv = wsf[dp];
#pragma unroll
        for (int c = 0; c < 8; c++) {
            unsigned t = tanh2(hadd2u(qq, Ksh[tx + 16 * c][dp]));
            float2 f = h2_to_f2(t);
            a[c] += wv.x * f.x + wv.y * f.y;
        }
    }

    float* Sb = g_S + (((size_t)b * Lx + i0 + ty) * Lx + j0);
#pragma unroll
    for (int c = 0; c < 8; c++)
        Sb[tx + 16 * c] = a[c];
}

// ---------------------------------------------------------------------------
// Kernel 3: softmax over j (scores pre-scaled by log2e -> exp2 direct)
// + out = attn @ x. 8 query rows per block (grid 256), 256 threads.
// Warp w owns softmax of row w; AV: thread owns column d for 4 rows.
// ---------------------------------------------------------------------------
__global__ __launch_bounds__(256) void out_kernel(const float* __restrict__ x,
                                                  float* __restrict__ out) {
    __shared__ float Ps[8][Lx];    // 16 KB
    __shared__ float linv[8];

    int row0 = blockIdx.x * 8;         // global row in [0, B*L)
    int bb = row0 >> 9;                // / L

    const float4* S4 = (const float4*)(g_S + (size_t)row0 * Lx);
    for (int t = threadIdx.x; t < 8 * Lx / 4; t += 256)
        ((float4*)Ps)[t] = S4[t];
    __syncthreads();

    int warp = threadIdx.x >> 5;   // row 0..7
    int lane = threadIdx.x & 31;
    {
        int r = warp;
        float v[16];
        float m = -1e30f;
#pragma unroll
        for (int c = 0; c < 16; c++) {
            v[c] = Ps[r][lane + c * 32];
            m = fmaxf(m, v[c]);
        }
#pragma unroll
        for (int o = 16; o; o >>= 1) m = fmaxf(m, __shfl_xor_sync(0xffffffffu, m, o));
        float s = 0.f;
#pragma unroll
        for (int c = 0; c < 16; c++) {
            float e = exp2f(v[c] - m);   // scores already include log2e
            s += e;
            Ps[r][lane + c * 32] = e;
        }
#pragma unroll
        for (int o = 16; o; o >>= 1) s += __shfl_xor_sync(0xffffffffu, s, o);
        if (lane == 0) linv[r] = 1.0f / s;
    }
    __syncthreads();

    int d = threadIdx.x & 127;
    int ig = threadIdx.x >> 7;   // 0 -> rows 0..3, 1 -> rows 4..7
    const float* xb = x + (size_t)bb * Lx * Dx;

    float acc[4] = {0.f, 0.f, 0.f, 0.f};

    for (int j = 0; j < Lx; j += 4) {
        float xv0 = xb[(size_t)(j + 0) * Dx + d];
        float xv1 = xb[(size_t)(j + 1) * Dx + d];
        float xv2 = xb[(size_t)(j + 2) * Dx + d];
        float xv3 = xb[(size_t)(j + 3) * Dx + d];
#pragma unroll
        for (int r = 0; r < 4; r++) {
            float4 p = *(const float4*)&Ps[ig * 4 + r][j];
            acc[r] += p.x * xv0 + p.y * xv1 + p.z * xv2 + p.w * xv3;
        }
    }

#pragma unroll
    for (int r = 0; r < 4; r++) {
        int row = row0 + ig * 4 + r;
        out[(size_t)row * Dx + d] = acc[r] * linv[ig * 4 + r];
    }
}

// ---------------------------------------------------------------------------
extern "C" void kernel_launch(void* const* d_in, const int* in_sizes, int n_in,
                              void* d_out, int out_size) {
    const float* x  = (const float*)d_in[0];
    // d_in[1] = mask (bool) — intentionally unused: reference's masked_fill is
    // out-of-place and discarded, so mask has no effect on the output.
    const float* Wq = (const float*)d_in[2];
    const float* bq = (const float*)d_in[3];
    const float* Wk = (const float*)d_in[4];
    const float* bk = (const float*)d_in[5];
    const float* w  = (const float*)d_in[6];
    // d_in[7] = bw — unused: constant score shift cancels in softmax.
    float* out = (float*)d_out;

    qk_kernel<<<Bx * Lx / 8, 256>>>(x, Wq, bq, Wk, bk);

    dim3 g2(Lx / 128, Lx / 16, Bx);
    score_kernel<<<g2, 256>>>(w);

    out_kernel<<<Bx * Lx / 8, 256>>>(x, out);
}